// round 8
// baseline (speedup 1.0000x reference)
#include <cuda_runtime.h>
#include <cuda_bf16.h>
#include <cstdint>

#define BQ 8
#define TT 1024
#define CC 768
#define HH 12
#define DD 64
#define MR (BQ*TT)
#define N3 (3*CC)

// Scratch (allocation-free rule: __device__ globals)
__device__ __align__(16) __nv_bfloat16 g_qh[(size_t)BQ*HH*TT*DD];
__device__ __align__(16) __nv_bfloat16 g_ql[(size_t)BQ*HH*TT*DD];
__device__ __align__(16) __nv_bfloat16 g_kh[(size_t)BQ*HH*TT*DD];
__device__ __align__(16) __nv_bfloat16 g_kl[(size_t)BQ*HH*TT*DD];
__device__ __align__(16) float g_v[(size_t)BQ*HH*TT*DD];   // V fp32
__device__ __align__(16) float g_y[(size_t)BQ*TT*CC];      // attn out fp32

// ---------------------------------------------------------------------------
// mma.sync m16n8k16 bf16 -> f32 (HMMA; family-PTX safe)
// ---------------------------------------------------------------------------
__device__ __forceinline__ void mma16816(float* d, const uint32_t* a, const uint32_t* b) {
    asm volatile(
        "mma.sync.aligned.m16n8k16.row.col.f32.bf16.bf16.f32 "
        "{%0,%1,%2,%3}, {%4,%5,%6,%7}, {%8,%9}, {%0,%1,%2,%3};\n"
        : "+f"(d[0]), "+f"(d[1]), "+f"(d[2]), "+f"(d[3])
        : "r"(a[0]), "r"(a[1]), "r"(a[2]), "r"(a[3]), "r"(b[0]), "r"(b[1]));
}

struct __align__(8) BF4 { __nv_bfloat16 a, b, c, d; };

__device__ __forceinline__ void cvt_split(float x, __nv_bfloat16& h, __nv_bfloat16& l) {
    h = __float2bfloat16(x);
    l = __float2bfloat16(x - __bfloat162float(h));
}

// fast 2^y for y <= 0, FMA-pipe only. ~1.5e-5 max rel error.
__device__ __forceinline__ float exp2p(float y) {
    y = fmaxf(y, -126.f);
    float fi = floorf(y);
    float f = y - fi;
    float p = 1.f + f * (0.6931472f + f * (0.2402265f + f * (0.0555041f +
              f * (0.0096181f + f * (0.0013334f + f * 0.0001546f)))));
    return __int_as_float(__float_as_int(p) + ((int)fi << 23));
}
#define LOG2E 1.4426950408889634f

// ---------------------------------------------------------------------------
// Tensor-core GEMM (R5-proven core): 128x128x32, bf16 hi/lo 3-pass, fp32 in.
// mode 0: X*Wattn -> scatter q/k (bf16 hi/lo split) + v (fp32)
// mode 1: g_y*Wproj -> out
// ---------------------------------------------------------------------------
#define PAD 40
#define A_MAT (128 * PAD)
#define STAGE_ELEMS (4 * A_MAT)
#define GEMM_SMEM (2 * STAGE_ELEMS * 2)

__global__ __launch_bounds__(256, 1) void tc_gemm_kernel(
    const float* __restrict__ A_in, const float* __restrict__ W,
    const float* __restrict__ bias, const float* __restrict__ rel,
    float* __restrict__ out, int ldw, int mode)
{
    extern __shared__ __nv_bfloat16 sm[];

    const float* A = (mode == 0) ? A_in : g_y;

    const int tid = threadIdx.x;
    const int wid = tid >> 5, lane = tid & 31;
    const int n0 = blockIdx.x * 128;
    const int m0 = blockIdx.y * 128;

    const int warp_m = wid & 1;
    const int warp_n = wid >> 1;
    const int lr = lane >> 2;
    const int lc = lane & 3;

    const int am = tid >> 1;
    const int akq = (tid & 1) * 16;
    const int bk0 = (tid >> 5) * 4;
    const int bn0 = (tid & 31) * 4;

    const float* Ag = A + (size_t)(m0 + am) * CC + akq;
    const float* Wg = W + (size_t)bk0 * ldw + n0 + bn0;

    float acc[4][4][4];
#pragma unroll
    for (int i = 0; i < 4; i++)
#pragma unroll
        for (int j = 0; j < 4; j++)
#pragma unroll
            for (int r = 0; r < 4; r++) acc[i][j][r] = 0.f;

    float4 pa[4];
    float4 pb[4];

    auto load_global = [&](int k0) {
#pragma unroll
        for (int c = 0; c < 4; c++)
            pa[c] = *(const float4*)(Ag + k0 + c * 4);
#pragma unroll
        for (int i = 0; i < 4; i++)
            pb[i] = *(const float4*)(Wg + (size_t)(k0 + i) * ldw);
    };

    auto store_smem = [&](int s) {
        __nv_bfloat16* base = sm + s * STAGE_ELEMS;
        __nv_bfloat16* sAhi = base;
        __nv_bfloat16* sAlo = base + A_MAT;
        __nv_bfloat16* sBhi = base + 2 * A_MAT;
        __nv_bfloat16* sBlo = base + 3 * A_MAT;
#pragma unroll
        for (int c = 0; c < 4; c++) {
            BF4 h, l;
            cvt_split(pa[c].x, h.a, l.a);
            cvt_split(pa[c].y, h.b, l.b);
            cvt_split(pa[c].z, h.c, l.c);
            cvt_split(pa[c].w, h.d, l.d);
            const int off = am * PAD + akq + c * 4;
            *(BF4*)(sAhi + off) = h;
            *(BF4*)(sAlo + off) = l;
        }
        float col[4][4] = {
            {pb[0].x, pb[1].x, pb[2].x, pb[3].x},
            {pb[0].y, pb[1].y, pb[2].y, pb[3].y},
            {pb[0].z, pb[1].z, pb[2].z, pb[3].z},
            {pb[0].w, pb[1].w, pb[2].w, pb[3].w}};
#pragma unroll
        for (int j = 0; j < 4; j++) {
            BF4 h, l;
            cvt_split(col[j][0], h.a, l.a);
            cvt_split(col[j][1], h.b, l.b);
            cvt_split(col[j][2], h.c, l.c);
            cvt_split(col[j][3], h.d, l.d);
            const int off = (bn0 + j) * PAD + bk0;
            *(BF4*)(sBhi + off) = h;
            *(BF4*)(sBlo + off) = l;
        }
    };

    load_global(0);
    store_smem(0);
    __syncthreads();

    const int arow0 = warp_m * 64 + lr;
    const int brow0 = warp_n * 32 + lr;
    const int kcol0 = lc * 2;

    for (int stage = 0; stage < 24; stage++) {
        if (stage < 23) load_global((stage + 1) * 32);

        const __nv_bfloat16* base = sm + (stage & 1) * STAGE_ELEMS;
        const __nv_bfloat16* sAhi = base;
        const __nv_bfloat16* sAlo = base + A_MAT;
        const __nv_bfloat16* sBhi = base + 2 * A_MAT;
        const __nv_bfloat16* sBlo = base + 3 * A_MAT;

#pragma unroll
        for (int ks = 0; ks < 2; ks++) {
            const int kc = ks * 16 + kcol0;
            uint32_t af[4][4], bh[4][2], bl[4][2];
#pragma unroll
            for (int mi = 0; mi < 4; mi++) {
                const int r = arow0 + mi * 16;
                af[mi][0] = *(const uint32_t*)(sAhi + r * PAD + kc);
                af[mi][1] = *(const uint32_t*)(sAhi + (r + 8) * PAD + kc);
                af[mi][2] = *(const uint32_t*)(sAhi + r * PAD + kc + 8);
                af[mi][3] = *(const uint32_t*)(sAhi + (r + 8) * PAD + kc + 8);
            }
#pragma unroll
            for (int ni = 0; ni < 4; ni++) {
                const int r = brow0 + ni * 8;
                bh[ni][0] = *(const uint32_t*)(sBhi + r * PAD + kc);
                bh[ni][1] = *(const uint32_t*)(sBhi + r * PAD + kc + 8);
                bl[ni][0] = *(const uint32_t*)(sBlo + r * PAD + kc);
                bl[ni][1] = *(const uint32_t*)(sBlo + r * PAD + kc + 8);
            }
#pragma unroll
            for (int mi = 0; mi < 4; mi++)
#pragma unroll
                for (int ni = 0; ni < 4; ni++)
                    mma16816(acc[mi][ni], af[mi], bh[ni]);
#pragma unroll
            for (int mi = 0; mi < 4; mi++)
#pragma unroll
                for (int ni = 0; ni < 4; ni++)
                    mma16816(acc[mi][ni], af[mi], bl[ni]);
#pragma unroll
            for (int mi = 0; mi < 4; mi++) {
                const int r = arow0 + mi * 16;
                af[mi][0] = *(const uint32_t*)(sAlo + r * PAD + kc);
                af[mi][1] = *(const uint32_t*)(sAlo + (r + 8) * PAD + kc);
                af[mi][2] = *(const uint32_t*)(sAlo + r * PAD + kc + 8);
                af[mi][3] = *(const uint32_t*)(sAlo + (r + 8) * PAD + kc + 8);
            }
#pragma unroll
            for (int mi = 0; mi < 4; mi++)
#pragma unroll
                for (int ni = 0; ni < 4; ni++)
                    mma16816(acc[mi][ni], af[mi], bh[ni]);
        }

        if (stage < 23) {
            store_smem((stage + 1) & 1);
            __syncthreads();
        }
    }

    // ---- Epilogue ----
    const int seg = (mode == 0) ? (n0 / CC) : 0;

#pragma unroll
    for (int mi = 0; mi < 4; mi++) {
#pragma unroll
        for (int half = 0; half < 2; half++) {
            const int r = m0 + warp_m * 64 + mi * 16 + lr + half * 8;
#pragma unroll
            for (int ni = 0; ni < 4; ni++) {
                const int gc = n0 + warp_n * 32 + ni * 8 + lc * 2;
                float2 v;
                v.x = acc[mi][ni][half * 2 + 0] + bias[gc];
                v.y = acc[mi][ni][half * 2 + 1] + bias[gc + 1];
                if (mode == 0) {
                    const int bb = r >> 10, t = r & 1023;
                    const int cl = gc - seg * CC;
                    const int h = cl >> 6, d = cl & 63;
                    const size_t idx = (((size_t)bb * HH + h) * TT + t) * DD + d;
                    if (seg == 0) {
                        v.x *= 0.125f; v.y *= 0.125f;
                        __nv_bfloat16 hx, lx, hy, ly;
                        cvt_split(v.x, hx, lx);
                        cvt_split(v.y, hy, ly);
                        __nv_bfloat162 h2 = {hx, hy}, l2 = {lx, ly};
                        *(__nv_bfloat162*)&g_qh[idx] = h2;
                        *(__nv_bfloat162*)&g_ql[idx] = l2;
                    } else if (seg == 1) {
                        if (t > 0) {
                            float2 rv = *(const float2*)&rel[(size_t)(t - 1) * DD + d];
                            v.x += rv.x; v.y += rv.y;
                        }
                        __nv_bfloat16 hx, lx, hy, ly;
                        cvt_split(v.x, hx, lx);
                        cvt_split(v.y, hy, ly);
                        __nv_bfloat162 h2 = {hx, hy}, l2 = {lx, ly};
                        *(__nv_bfloat162*)&g_kh[idx] = h2;
                        *(__nv_bfloat162*)&g_kl[idx] = l2;
                    } else {
                        *(float2*)&g_v[idx] = v;
                    }
                } else {
                    *(float2*)&out[(size_t)r * CC + gc] = v;
                }
            }
        }
    }
}

// ---------------------------------------------------------------------------
// HMMA causal flash attention (R5 core). Q/K now arrive pre-split bf16 and
// are copied directly into smem; V fp32 split on load; output fp32 g_y.
// ---------------------------------------------------------------------------
#define FPAD 72

struct FlashSmem {
    __nv_bfloat16 Qh[64][FPAD], Ql[64][FPAD];
    __nv_bfloat16 Kh[64][FPAD], Kl[64][FPAD];
    __nv_bfloat16 Vh[64][FPAD], Vl[64][FPAD];   // V^T hi/lo: [d][j]
};

__global__ __launch_bounds__(128, 2) void flash_kernel()
{
    extern __shared__ char fsm_raw[];
    FlashSmem* S = reinterpret_cast<FlashSmem*>(fsm_raw);

    const int it = gridDim.x - 1 - blockIdx.x;   // heaviest first
    const int bh = blockIdx.y;
    const size_t hb = (size_t)bh * TT * DD;
    const float* Vg = g_v + hb;

    const int tid = threadIdx.x;
    const int warp = tid >> 5, lane = tid & 31;
    const int lr = lane >> 2, lc = lane & 3;

    // ---- Copy Q tile (pre-split bf16, direct uint4 copy) ----
    {
        const __nv_bfloat16* qhg = g_qh + hb + (size_t)it * 64 * DD;
        const __nv_bfloat16* qlg = g_ql + hb + (size_t)it * 64 * DD;
#pragma unroll
        for (int b = 0; b < 4; b++) {
            const int idx = tid + b * 128;
            const int row = idx >> 3, c8 = (idx & 7) * 8;
            *(uint4*)&S->Qh[row][c8] = *(const uint4*)(qhg + row * DD + c8);
            *(uint4*)&S->Ql[row][c8] = *(const uint4*)(qlg + row * DD + c8);
        }
    }
    __syncthreads();

    // ---- Q fragments in registers (invariant) ----
    uint32_t qh[4][4], ql[4][4];
    const int qr = warp * 16 + lr;
#pragma unroll
    for (int t = 0; t < 4; t++) {
        const int kc = t * 16 + lc * 2;
        qh[t][0] = *(const uint32_t*)&S->Qh[qr][kc];
        qh[t][1] = *(const uint32_t*)&S->Qh[qr + 8][kc];
        qh[t][2] = *(const uint32_t*)&S->Qh[qr][kc + 8];
        qh[t][3] = *(const uint32_t*)&S->Qh[qr + 8][kc + 8];
        ql[t][0] = *(const uint32_t*)&S->Ql[qr][kc];
        ql[t][1] = *(const uint32_t*)&S->Ql[qr + 8][kc];
        ql[t][2] = *(const uint32_t*)&S->Ql[qr][kc + 8];
        ql[t][3] = *(const uint32_t*)&S->Ql[qr + 8][kc + 8];
    }

    float o[8][4];
#pragma unroll
    for (int nt = 0; nt < 8; nt++)
#pragma unroll
        for (int r = 0; r < 4; r++) o[nt][r] = 0.f;
    float m_run[2] = {-1e30f, -1e30f};
    float l_run[2] = {0.f, 0.f};

    for (int jt = 0; jt <= it; jt++) {
        __syncthreads();
        // ---- K copy (pre-split bf16, direct) ----
        {
            const __nv_bfloat16* khg = g_kh + hb + (size_t)jt * 64 * DD;
            const __nv_bfloat16* klg = g_kl + hb + (size_t)jt * 64 * DD;
#pragma unroll
            for (int b = 0; b < 4; b++) {
                const int idx = tid + b * 128;
                const int row = idx >> 3, c8 = (idx & 7) * 8;
                *(uint4*)&S->Kh[row][c8] = *(const uint4*)(khg + row * DD + c8);
                *(uint4*)&S->Kl[row][c8] = *(const uint4*)(klg + row * DD + c8);
            }
        }
        // ---- V load fp32, split + transpose ----
#pragma unroll
        for (int b = 0; b < 2; b++) {
            const int bi = tid + b * 128;
            const int jr = (bi >> 4) * 4, dc = (bi & 15) * 4;
            const float* vp = Vg + (size_t)(jt * 64 + jr) * DD + dc;
            float4 r0 = *(const float4*)(vp);
            float4 r1 = *(const float4*)(vp + DD);
            float4 r2 = *(const float4*)(vp + 2 * DD);
            float4 r3 = *(const float4*)(vp + 3 * DD);
            float col[4][4] = {
                {r0.x, r1.x, r2.x, r3.x},
                {r0.y, r1.y, r2.y, r3.y},
                {r0.z, r1.z, r2.z, r3.z},
                {r0.w, r1.w, r2.w, r3.w}};
#pragma unroll
            for (int j = 0; j < 4; j++) {
                BF4 h, l;
                cvt_split(col[j][0], h.a, l.a);
                cvt_split(col[j][1], h.b, l.b);
                cvt_split(col[j][2], h.c, l.c);
                cvt_split(col[j][3], h.d, l.d);
                *(BF4*)&S->Vh[dc + j][jr] = h;
                *(BF4*)&S->Vl[dc + j][jr] = l;
            }
        }
        __syncthreads();

        // ---- S = Q K^T (3-pass split) ----
        float s[8][4];
#pragma unroll
        for (int nt = 0; nt < 8; nt++)
#pragma unroll
            for (int r = 0; r < 4; r++) s[nt][r] = 0.f;
#pragma unroll
        for (int nt = 0; nt < 8; nt++) {
            const int kr = nt * 8 + lr;
#pragma unroll
            for (int t = 0; t < 4; t++) {
                const int kc = t * 16 + lc * 2;
                uint32_t bhf[2], blf[2];
                bhf[0] = *(const uint32_t*)&S->Kh[kr][kc];
                bhf[1] = *(const uint32_t*)&S->Kh[kr][kc + 8];
                blf[0] = *(const uint32_t*)&S->Kl[kr][kc];
                blf[1] = *(const uint32_t*)&S->Kl[kr][kc + 8];
                mma16816(s[nt], qh[t], bhf);
                mma16816(s[nt], qh[t], blf);
                mma16816(s[nt], ql[t], bhf);
            }
        }

        // ---- causal mask on diagonal tile ----
        if (jt == it) {
#pragma unroll
            for (int nt = 0; nt < 8; nt++) {
#pragma unroll
                for (int r = 0; r < 4; r++) {
                    const int col = nt * 8 + lc * 2 + (r & 1);
                    const int row = warp * 16 + lr + ((r >> 1) * 8);
                    if (col > row) s[nt][r] = -1e30f;
                }
            }
        }

        // ---- row max, quad shuffle reduce ----
        float mnew[2], fscale[2];
#pragma unroll
        for (int h = 0; h < 2; h++) {
            float m = -1e30f;
#pragma unroll
            for (int nt = 0; nt < 8; nt++)
                m = fmaxf(m, fmaxf(s[nt][h * 2], s[nt][h * 2 + 1]));
            m = fmaxf(m, __shfl_xor_sync(0xFFFFFFFF, m, 1));
            m = fmaxf(m, __shfl_xor_sync(0xFFFFFFFF, m, 2));
            mnew[h] = fmaxf(m_run[h], m);
            fscale[h] = exp2p((m_run[h] - mnew[h]) * LOG2E);
            m_run[h] = mnew[h];
        }

        // ---- p = exp(s - m), row sums ----
        float rsum[2] = {0.f, 0.f};
#pragma unroll
        for (int nt = 0; nt < 8; nt++) {
#pragma unroll
            for (int r = 0; r < 4; r++) {
                const int h = r >> 1;
                float p = exp2p((s[nt][r] - mnew[h]) * LOG2E);
                s[nt][r] = p;
                rsum[h] += p;
            }
        }
#pragma unroll
        for (int h = 0; h < 2; h++) {
            rsum[h] += __shfl_xor_sync(0xFFFFFFFF, rsum[h], 1);
            rsum[h] += __shfl_xor_sync(0xFFFFFFFF, rsum[h], 2);
            l_run[h] = l_run[h] * fscale[h] + rsum[h];
        }

        // ---- rescale O ----
#pragma unroll
        for (int nt = 0; nt < 8; nt++) {
#pragma unroll
            for (int r = 0; r < 4; r++) o[nt][r] *= fscale[r >> 1];
        }

        // ---- pack P hi/lo fragments ----
        uint32_t pfh[4][4], pfl[4][4];
#pragma unroll
        for (int t = 0; t < 4; t++) {
            __nv_bfloat16 h00, l00, h01, l01, h10, l10, h11, l11;
            cvt_split(s[2 * t][0], h00, l00);
            cvt_split(s[2 * t][1], h01, l01);
            cvt_split(s[2 * t][2], h10, l10);
            cvt_split(s[2 * t][3], h11, l11);
            __nv_bfloat162 ph0 = {h00, h01}, pl0 = {l00, l01};
            __nv_bfloat162 ph1 = {h10, h11}, pl1 = {l10, l11};
            __nv_bfloat16 h20, l20, h21, l21, h30, l30, h31, l31;
            cvt_split(s[2 * t + 1][0], h20, l20);
            cvt_split(s[2 * t + 1][1], h21, l21);
            cvt_split(s[2 * t + 1][2], h30, l30);
            cvt_split(s[2 * t + 1][3], h31, l31);
            __nv_bfloat162 ph2 = {h20, h21}, pl2 = {l20, l21};
            __nv_bfloat162 ph3 = {h30, h31}, pl3 = {l30, l31};
            pfh[t][0] = *(uint32_t*)&ph0;
            pfh[t][1] = *(uint32_t*)&ph1;
            pfh[t][2] = *(uint32_t*)&ph2;
            pfh[t][3] = *(uint32_t*)&ph3;
            pfl[t][0] = *(uint32_t*)&pl0;
            pfl[t][1] = *(uint32_t*)&pl1;
            pfl[t][2] = *(uint32_t*)&pl2;
            pfl[t][3] = *(uint32_t*)&pl3;
        }

        // ---- O += P V (3-pass split) ----
#pragma unroll
        for (int dt = 0; dt < 8; dt++) {
            const int vr = dt * 8 + lr;
#pragma unroll
            for (int t = 0; t < 4; t++) {
                const int jc = t * 16 + lc * 2;
                uint32_t bhf[2], blf[2];
                bhf[0] = *(const uint32_t*)&S->Vh[vr][jc];
                bhf[1] = *(const uint32_t*)&S->Vh[vr][jc + 8];
                blf[0] = *(const uint32_t*)&S->Vl[vr][jc];
                blf[1] = *(const uint32_t*)&S->Vl[vr][jc + 8];
                mma16816(o[dt], pfh[t], bhf);
                mma16816(o[dt], pfh[t], blf);
                mma16816(o[dt], pfl[t], bhf);
            }
        }
    }

    // ---- Output: y[b, t, h*64 + d] = o / l (fp32, R5-proven) ----
    const int hh = bh % HH, bb = bh / HH;
    const float inv0 = 1.0f / l_run[0];
    const float inv1 = 1.0f / l_run[1];
    const int row0 = it * 64 + warp * 16 + lr;
#pragma unroll
    for (int nt = 0; nt < 8; nt++) {
        const int d = nt * 8 + lc * 2;
        float2 v0 = make_float2(o[nt][0] * inv0, o[nt][1] * inv0);
        float2 v1 = make_float2(o[nt][2] * inv1, o[nt][3] * inv1);
        *(float2*)&g_y[((size_t)bb * TT + row0) * CC + hh * DD + d] = v0;
        *(float2*)&g_y[((size_t)bb * TT + row0 + 8) * CC + hh * DD + d] = v1;
    }
}

// ---------------------------------------------------------------------------
extern "C" void kernel_launch(void* const* d_in, const int* in_sizes, int n_in,
                              void* d_out, int out_size)
{
    const float* x      = (const float*)d_in[0];
    const float* w_attn = (const float*)d_in[1];
    const float* b_attn = (const float*)d_in[2];
    const float* w_proj = (const float*)d_in[3];
    const float* b_proj = (const float*)d_in[4];
    const float* rel    = (const float*)d_in[5];
    float* out = (float*)d_out;

    cudaFuncSetAttribute(tc_gemm_kernel,
                         cudaFuncAttributeMaxDynamicSharedMemorySize, GEMM_SMEM);
    cudaFuncSetAttribute(flash_kernel,
                         cudaFuncAttributeMaxDynamicSharedMemorySize,
                         (int)sizeof(FlashSmem));

    tc_gemm_kernel<<<dim3(N3 / 128, MR / 128), 256, GEMM_SMEM>>>(
        x, w_attn, b_attn, rel, nullptr, N3, 0);
    flash_kernel<<<dim3(TT / 64, BQ * HH), 128, sizeof(FlashSmem)>>>();
    tc_gemm_kernel<<<dim3(CC / 128, MR / 128), 256, GEMM_SMEM>>>(
        x, w_proj, b_proj, rel, out, CC, 1);
}

// round 10
// speedup vs baseline: 1.0213x; 1.0213x over previous
#include <cuda_runtime.h>
#include <cuda_bf16.h>
#include <cstdint>

#define BQ 8
#define TT 1024
#define CC 768
#define HH 12
#define DD 64
#define MR (BQ*TT)
#define N3 (3*CC)

// Scratch (allocation-free rule: __device__ globals)
__device__ __align__(16) __nv_bfloat16 g_xh[(size_t)MR*CC], g_xl[(size_t)MR*CC];
__device__ __align__(16) __nv_bfloat16 g_wth[(size_t)N3*CC], g_wtl[(size_t)N3*CC];
__device__ __align__(16) __nv_bfloat16 g_pth[(size_t)CC*CC], g_ptl[(size_t)CC*CC];
__device__ __align__(16) __nv_bfloat16 g_qh[(size_t)BQ*HH*TT*DD], g_ql[(size_t)BQ*HH*TT*DD];
__device__ __align__(16) __nv_bfloat16 g_kh[(size_t)BQ*HH*TT*DD], g_kl[(size_t)BQ*HH*TT*DD];
__device__ __align__(16) float g_v[(size_t)BQ*HH*TT*DD];
__device__ __align__(16) __nv_bfloat16 g_yh[(size_t)MR*CC], g_yl[(size_t)MR*CC];

// ---------------------------------------------------------------------------
// helpers
// ---------------------------------------------------------------------------
__device__ __forceinline__ void mma16816(float* d, const uint32_t* a, const uint32_t* b) {
    asm volatile(
        "mma.sync.aligned.m16n8k16.row.col.f32.bf16.bf16.f32 "
        "{%0,%1,%2,%3}, {%4,%5,%6,%7}, {%8,%9}, {%0,%1,%2,%3};\n"
        : "+f"(d[0]), "+f"(d[1]), "+f"(d[2]), "+f"(d[3])
        : "r"(a[0]), "r"(a[1]), "r"(a[2]), "r"(a[3]), "r"(b[0]), "r"(b[1]));
}

struct __align__(8) BF4 { __nv_bfloat16 a, b, c, d; };

__device__ __forceinline__ void cvt_split(float x, __nv_bfloat16& h, __nv_bfloat16& l) {
    h = __float2bfloat16(x);
    l = __float2bfloat16(x - __bfloat162float(h));
}

// fast 2^y for y <= 0, FMA-pipe only. ~1.5e-5 max rel error.
__device__ __forceinline__ float exp2p(float y) {
    y = fmaxf(y, -126.f);
    float fi = floorf(y);
    float f = y - fi;
    float p = 1.f + f * (0.6931472f + f * (0.2402265f + f * (0.0555041f +
              f * (0.0096181f + f * (0.0013334f + f * 0.0001546f)))));
    return __int_as_float(__float_as_int(p) + ((int)fi << 23));
}
#define LOG2E 1.4426950408889634f

// ---------------------------------------------------------------------------
// Split X elementwise: fp32 -> bf16 hi/lo (globals referenced in device code)
// ---------------------------------------------------------------------------
__global__ void split_x_kernel(const float* __restrict__ x) {
    const size_t i = ((size_t)blockIdx.x * 256 + threadIdx.x) * 4;
    float4 v = *(const float4*)(x + i);
    BF4 h, l;
    cvt_split(v.x, h.a, l.a);
    cvt_split(v.y, h.b, l.b);
    cvt_split(v.z, h.c, l.c);
    cvt_split(v.w, h.d, l.d);
    *(BF4*)&g_xh[i] = h;
    *(BF4*)&g_xl[i] = l;
}

// ---------------------------------------------------------------------------
// Transpose + split: W [768][N] fp32 -> [N][768] bf16 hi/lo.
// FIX vs R9: destination device-global arrays selected INSIDE device code
// (passing __device__ symbols as host-side kernel args gives the host shadow
// address -> illegal store -> the R6/R7/R9 failures).
// ---------------------------------------------------------------------------
__global__ void tsplit_kernel(const float* __restrict__ W, int N, int which) {
    __nv_bfloat16* outh = (which == 0) ? g_wth : g_pth;
    __nv_bfloat16* outl = (which == 0) ? g_wtl : g_ptl;
    __shared__ float t[32][33];
    const int n0 = blockIdx.x * 32, k0 = blockIdx.y * 32;
    const int tx = threadIdx.x & 31, ty = threadIdx.x >> 5;
#pragma unroll
    for (int i = 0; i < 4; i++)
        t[ty + i * 8][tx] = W[(size_t)(k0 + ty + i * 8) * N + n0 + tx];
    __syncthreads();
#pragma unroll
    for (int i = 0; i < 4; i++) {
        float v = t[tx][ty + i * 8];
        __nv_bfloat16 h, l;
        cvt_split(v, h, l);
        const size_t o = (size_t)(n0 + ty + i * 8) * CC + k0 + tx;
        outh[o] = h;
        outl[o] = l;
    }
}

// ---------------------------------------------------------------------------
// HMMA GEMM on pre-split bf16: C[8192 x N] = A * B^T (+bias)
// BM=BN=128, BK=32; 256 thr = 8 warps (2m x 4n); register-prefetch double
// buffer; 3-pass hi/lo split; occupancy 2 (pure-bf16 staging, no cvt).
// mode 0: X*Wattn -> scatter q/k (bf16 split) + v (fp32); mode 1: Y*Wproj.
// ---------------------------------------------------------------------------
#define PAD 40
#define A_MAT (128 * PAD)                 // bf16 elems per matrix
#define STAGE_ELEMS (4 * A_MAT)           // Ahi, Alo, Bhi, Blo
#define GEMM_SMEM (2 * STAGE_ELEMS * 2)   // bytes (81920)

__global__ __launch_bounds__(256, 2) void tc_gemm_kernel(
    const float* __restrict__ bias, const float* __restrict__ rel,
    float* __restrict__ out, int mode)
{
    extern __shared__ __nv_bfloat16 sm[];

    const __nv_bfloat16* Ah = (mode == 0) ? g_xh : g_yh;
    const __nv_bfloat16* Al = (mode == 0) ? g_xl : g_yl;
    const __nv_bfloat16* Bh = (mode == 0) ? g_wth : g_pth;
    const __nv_bfloat16* Bl = (mode == 0) ? g_wtl : g_ptl;

    const int tid = threadIdx.x;
    const int wid = tid >> 5, lane = tid & 31;
    const int n0 = blockIdx.x * 128;
    const int m0 = blockIdx.y * 128;

    const int warp_m = wid & 1;
    const int warp_n = wid >> 1;
    const int lr = lane >> 2;
    const int lc = lane & 3;

    // copy mapping: row = tid>>1 (0..127), k-offset = (tid&1)*16
    const int crow = tid >> 1;
    const int cko = (tid & 1) * 16;
    const int s_off = crow * PAD + cko;
    const __nv_bfloat16* gAh = Ah + (size_t)(m0 + crow) * CC + cko;
    const __nv_bfloat16* gAl = Al + (size_t)(m0 + crow) * CC + cko;
    const __nv_bfloat16* gBh = Bh + (size_t)(n0 + crow) * CC + cko;
    const __nv_bfloat16* gBl = Bl + (size_t)(n0 + crow) * CC + cko;

    float acc[4][4][4];
#pragma unroll
    for (int i = 0; i < 4; i++)
#pragma unroll
        for (int j = 0; j < 4; j++)
#pragma unroll
            for (int r = 0; r < 4; r++) acc[i][j][r] = 0.f;

    uint4 rA[4], rB[4];   // [Ah0, Ah1, Al0, Al1], [Bh0, Bh1, Bl0, Bl1]

    auto load_global = [&](int k0) {
        rA[0] = *(const uint4*)(gAh + k0);
        rA[1] = *(const uint4*)(gAh + k0 + 8);
        rA[2] = *(const uint4*)(gAl + k0);
        rA[3] = *(const uint4*)(gAl + k0 + 8);
        rB[0] = *(const uint4*)(gBh + k0);
        rB[1] = *(const uint4*)(gBh + k0 + 8);
        rB[2] = *(const uint4*)(gBl + k0);
        rB[3] = *(const uint4*)(gBl + k0 + 8);
    };

    auto store_smem = [&](int buf) {
        __nv_bfloat16* base = sm + buf * STAGE_ELEMS;
        *(uint4*)(base + s_off) = rA[0];
        *(uint4*)(base + s_off + 8) = rA[1];
        *(uint4*)(base + A_MAT + s_off) = rA[2];
        *(uint4*)(base + A_MAT + s_off + 8) = rA[3];
        *(uint4*)(base + 2 * A_MAT + s_off) = rB[0];
        *(uint4*)(base + 2 * A_MAT + s_off + 8) = rB[1];
        *(uint4*)(base + 3 * A_MAT + s_off) = rB[2];
        *(uint4*)(base + 3 * A_MAT + s_off + 8) = rB[3];
    };

    load_global(0);
    store_smem(0);
    __syncthreads();

    const int arow0 = warp_m * 64 + lr;
    const int brow0 = warp_n * 32 + lr;
    const int kcol0 = lc * 2;

    for (int s = 0; s < 24; s++) {
        if (s < 23) load_global((s + 1) * 32);

        const __nv_bfloat16* base = sm + (s & 1) * STAGE_ELEMS;
        const __nv_bfloat16* sAh = base;
        const __nv_bfloat16* sAl = base + A_MAT;
        const __nv_bfloat16* sBh = base + 2 * A_MAT;
        const __nv_bfloat16* sBl = base + 3 * A_MAT;

#pragma unroll
        for (int ks = 0; ks < 2; ks++) {
            const int kc = ks * 16 + kcol0;
            uint32_t af[4][4], bh[4][2], bl[4][2];
#pragma unroll
            for (int mi = 0; mi < 4; mi++) {
                const int r = arow0 + mi * 16;
                af[mi][0] = *(const uint32_t*)(sAh + r * PAD + kc);
                af[mi][1] = *(const uint32_t*)(sAh + (r + 8) * PAD + kc);
                af[mi][2] = *(const uint32_t*)(sAh + r * PAD + kc + 8);
                af[mi][3] = *(const uint32_t*)(sAh + (r + 8) * PAD + kc + 8);
            }
#pragma unroll
            for (int ni = 0; ni < 4; ni++) {
                const int r = brow0 + ni * 8;
                bh[ni][0] = *(const uint32_t*)(sBh + r * PAD + kc);
                bh[ni][1] = *(const uint32_t*)(sBh + r * PAD + kc + 8);
                bl[ni][0] = *(const uint32_t*)(sBl + r * PAD + kc);
                bl[ni][1] = *(const uint32_t*)(sBl + r * PAD + kc + 8);
            }
#pragma unroll
            for (int mi = 0; mi < 4; mi++)
#pragma unroll
                for (int ni = 0; ni < 4; ni++)
                    mma16816(acc[mi][ni], af[mi], bh[ni]);
#pragma unroll
            for (int mi = 0; mi < 4; mi++)
#pragma unroll
                for (int ni = 0; ni < 4; ni++)
                    mma16816(acc[mi][ni], af[mi], bl[ni]);
#pragma unroll
            for (int mi = 0; mi < 4; mi++) {
                const int r = arow0 + mi * 16;
                af[mi][0] = *(const uint32_t*)(sAl + r * PAD + kc);
                af[mi][1] = *(const uint32_t*)(sAl + (r + 8) * PAD + kc);
                af[mi][2] = *(const uint32_t*)(sAl + r * PAD + kc + 8);
                af[mi][3] = *(const uint32_t*)(sAl + (r + 8) * PAD + kc + 8);
            }
#pragma unroll
            for (int mi = 0; mi < 4; mi++)
#pragma unroll
                for (int ni = 0; ni < 4; ni++)
                    mma16816(acc[mi][ni], af[mi], bh[ni]);
        }

        if (s < 23) {
            store_smem((s + 1) & 1);
            __syncthreads();
        }
    }

    // ---- Epilogue (R8-proven) ----
    const int seg = (mode == 0) ? (n0 / CC) : 0;

#pragma unroll
    for (int mi = 0; mi < 4; mi++) {
#pragma unroll
        for (int half = 0; half < 2; half++) {
            const int r = m0 + warp_m * 64 + mi * 16 + lr + half * 8;
#pragma unroll
            for (int ni = 0; ni < 4; ni++) {
                const int gc = n0 + warp_n * 32 + ni * 8 + lc * 2;
                float2 v;
                v.x = acc[mi][ni][half * 2 + 0] + bias[gc];
                v.y = acc[mi][ni][half * 2 + 1] + bias[gc + 1];
                if (mode == 0) {
                    const int bb = r >> 10, t = r & 1023;
                    const int cl = gc - seg * CC;
                    const int h = cl >> 6, d = cl & 63;
                    const size_t idx = (((size_t)bb * HH + h) * TT + t) * DD + d;
                    if (seg == 0) {
                        v.x *= 0.125f; v.y *= 0.125f;
                        __nv_bfloat16 hx, lx, hy, ly;
                        cvt_split(v.x, hx, lx);
                        cvt_split(v.y, hy, ly);
                        __nv_bfloat162 h2 = {hx, hy}, l2 = {lx, ly};
                        *(__nv_bfloat162*)&g_qh[idx] = h2;
                        *(__nv_bfloat162*)&g_ql[idx] = l2;
                    } else if (seg == 1) {
                        if (t > 0) {
                            float2 rv = *(const float2*)&rel[(size_t)(t - 1) * DD + d];
                            v.x += rv.x; v.y += rv.y;
                        }
                        __nv_bfloat16 hx, lx, hy, ly;
                        cvt_split(v.x, hx, lx);
                        cvt_split(v.y, hy, ly);
                        __nv_bfloat162 h2 = {hx, hy}, l2 = {lx, ly};
                        *(__nv_bfloat162*)&g_kh[idx] = h2;
                        *(__nv_bfloat162*)&g_kl[idx] = l2;
                    } else {
                        *(float2*)&g_v[idx] = v;
                    }
                } else {
                    *(float2*)&out[(size_t)r * CC + gc] = v;
                }
            }
        }
    }
}

// ---------------------------------------------------------------------------
// HMMA causal flash attention (R8-proven body). Q/K pre-split bf16, direct
// copies; V fp32 split on load; output written as bf16 hi/lo for proj GEMM.
// ---------------------------------------------------------------------------
#define FPAD 72

struct FlashSmem {
    __nv_bfloat16 Qh[64][FPAD], Ql[64][FPAD];
    __nv_bfloat16 Kh[64][FPAD], Kl[64][FPAD];
    __nv_bfloat16 Vh[64][FPAD], Vl[64][FPAD];   // V^T hi/lo: [d][j]
};

__global__ __launch_bounds__(128, 2) void flash_kernel()
{
    extern __shared__ char fsm_raw[];
    FlashSmem* S = reinterpret_cast<FlashSmem*>(fsm_raw);

    const int it = gridDim.x - 1 - blockIdx.x;   // heaviest first
    const int bh = blockIdx.y;
    const size_t hb = (size_t)bh * TT * DD;
    const float* Vg = g_v + hb;

    const int tid = threadIdx.x;
    const int warp = tid >> 5, lane = tid & 31;
    const int lr = lane >> 2, lc = lane & 3;

    // ---- Copy Q tile (pre-split bf16, direct uint4 copy) ----
    {
        const __nv_bfloat16* qhg = g_qh + hb + (size_t)it * 64 * DD;
        const __nv_bfloat16* qlg = g_ql + hb + (size_t)it * 64 * DD;
#pragma unroll
        for (int b = 0; b < 4; b++) {
            const int idx = tid + b * 128;
            const int row = idx >> 3, c8 = (idx & 7) * 8;
            *(uint4*)&S->Qh[row][c8] = *(const uint4*)(qhg + row * DD + c8);
            *(uint4*)&S->Ql[row][c8] = *(const uint4*)(qlg + row * DD + c8);
        }
    }
    __syncthreads();

    // ---- Q fragments in registers (invariant) ----
    uint32_t qh[4][4], ql[4][4];
    const int qr = warp * 16 + lr;
#pragma unroll
    for (int t = 0; t < 4; t++) {
        const int kc = t * 16 + lc * 2;
        qh[t][0] = *(const uint32_t*)&S->Qh[qr][kc];
        qh[t][1] = *(const uint32_t*)&S->Qh[qr + 8][kc];
        qh[t][2] = *(const uint32_t*)&S->Qh[qr][kc + 8];
        qh[t][3] = *(const uint32_t*)&S->Qh[qr + 8][kc + 8];
        ql[t][0] = *(const uint32_t*)&S->Ql[qr][kc];
        ql[t][1] = *(const uint32_t*)&S->Ql[qr + 8][kc];
        ql[t][2] = *(const uint32_t*)&S->Ql[qr][kc + 8];
        ql[t][3] = *(const uint32_t*)&S->Ql[qr + 8][kc + 8];
    }

    float o[8][4];
#pragma unroll
    for (int nt = 0; nt < 8; nt++)
#pragma unroll
        for (int r = 0; r < 4; r++) o[nt][r] = 0.f;
    float m_run[2] = {-1e30f, -1e30f};
    float l_run[2] = {0.f, 0.f};

    for (int jt = 0; jt <= it; jt++) {
        __syncthreads();
        // ---- K copy (pre-split bf16, direct) ----
        {
            const __nv_bfloat16* khg = g_kh + hb + (size_t)jt * 64 * DD;
            const __nv_bfloat16* klg = g_kl + hb + (size_t)jt * 64 * DD;
#pragma unroll
            for (int b = 0; b < 4; b++) {
                const int idx = tid + b * 128;
                const int row = idx >> 3, c8 = (idx & 7) * 8;
                *(uint4*)&S->Kh[row][c8] = *(const uint4*)(khg + row * DD + c8);
                *(uint4*)&S->Kl[row][c8] = *(const uint4*)(klg + row * DD + c8);
            }
        }
        // ---- V load fp32, split + transpose ----
#pragma unroll
        for (int b = 0; b < 2; b++) {
            const int bi = tid + b * 128;
            const int jr = (bi >> 4) * 4, dc = (bi & 15) * 4;
            const float* vp = Vg + (size_t)(jt * 64 + jr) * DD + dc;
            float4 r0 = *(const float4*)(vp);
            float4 r1 = *(const float4*)(vp + DD);
            float4 r2 = *(const float4*)(vp + 2 * DD);
            float4 r3 = *(const float4*)(vp + 3 * DD);
            float col[4][4] = {
                {r0.x, r1.x, r2.x, r3.x},
                {r0.y, r1.y, r2.y, r3.y},
                {r0.z, r1.z, r2.z, r3.z},
                {r0.w, r1.w, r2.w, r3.w}};
#pragma unroll
            for (int j = 0; j < 4; j++) {
                BF4 h, l;
                cvt_split(col[j][0], h.a, l.a);
                cvt_split(col[j][1], h.b, l.b);
                cvt_split(col[j][2], h.c, l.c);
                cvt_split(col[j][3], h.d, l.d);
                *(BF4*)&S->Vh[dc + j][jr] = h;
                *(BF4*)&S->Vl[dc + j][jr] = l;
            }
        }
        __syncthreads();

        // ---- S = Q K^T (3-pass split) ----
        float s[8][4];
#pragma unroll
        for (int nt = 0; nt < 8; nt++)
#pragma unroll
            for (int r = 0; r < 4; r++) s[nt][r] = 0.f;
#pragma unroll
        for (int nt = 0; nt < 8; nt++) {
            const int kr = nt * 8 + lr;
#pragma unroll
            for (int t = 0; t < 4; t++) {
                const int kc = t * 16 + lc * 2;
                uint32_t bhf[2], blf[2];
                bhf[0] = *(const uint32_t*)&S->Kh[kr][kc];
                bhf[1] = *(const uint32_t*)&S->Kh[kr][kc + 8];
                blf[0] = *(const uint32_t*)&S->Kl[kr][kc];
                blf[1] = *(const uint32_t*)&S->Kl[kr][kc + 8];
                mma16816(s[nt], qh[t], bhf);
                mma16816(s[nt], qh[t], blf);
                mma16816(s[nt], ql[t], bhf);
            }
        }

        // ---- causal mask on diagonal tile ----
        if (jt == it) {
#pragma unroll
            for (int nt = 0; nt < 8; nt++) {
#pragma unroll
                for (int r = 0; r < 4; r++) {
                    const int col = nt * 8 + lc * 2 + (r & 1);
                    const int row = warp * 16 + lr + ((r >> 1) * 8);
                    if (col > row) s[nt][r] = -1e30f;
                }
            }
        }

        // ---- row max, quad shuffle reduce ----
        float mnew[2], fscale[2];
#pragma unroll
        for (int h = 0; h < 2; h++) {
            float m = -1e30f;
#pragma unroll
            for (int nt = 0; nt < 8; nt++)
                m = fmaxf(m, fmaxf(s[nt][h * 2], s[nt][h * 2 + 1]));
            m = fmaxf(m, __shfl_xor_sync(0xFFFFFFFF, m, 1));
            m = fmaxf(m, __shfl_xor_sync(0xFFFFFFFF, m, 2));
            mnew[h] = fmaxf(m_run[h], m);
            fscale[h] = exp2p((m_run[h] - mnew[h]) * LOG2E);
            m_run[h] = mnew[h];
        }

        // ---- p = exp(s - m), row sums ----
        float rsum[2] = {0.f, 0.f};
#pragma unroll
        for (int nt = 0; nt < 8; nt++) {
#pragma unroll
            for (int r = 0; r < 4; r++) {
                const int h = r >> 1;
                float p = exp2p((s[nt][r] - mnew[h]) * LOG2E);
                s[nt][r] = p;
                rsum[h] += p;
            }
        }
#pragma unroll
        for (int h = 0; h < 2; h++) {
            rsum[h] += __shfl_xor_sync(0xFFFFFFFF, rsum[h], 1);
            rsum[h] += __shfl_xor_sync(0xFFFFFFFF, rsum[h], 2);
            l_run[h] = l_run[h] * fscale[h] + rsum[h];
        }

        // ---- rescale O ----
#pragma unroll
        for (int nt = 0; nt < 8; nt++) {
#pragma unroll
            for (int r = 0; r < 4; r++) o[nt][r] *= fscale[r >> 1];
        }

        // ---- pack P hi/lo fragments ----
        uint32_t pfh[4][4], pfl[4][4];
#pragma unroll
        for (int t = 0; t < 4; t++) {
            __nv_bfloat16 h00, l00, h01, l01, h10, l10, h11, l11;
            cvt_split(s[2 * t][0], h00, l00);
            cvt_split(s[2 * t][1], h01, l01);
            cvt_split(s[2 * t][2], h10, l10);
            cvt_split(s[2 * t][3], h11, l11);
            __nv_bfloat162 ph0 = {h00, h01}, pl0 = {l00, l01};
            __nv_bfloat162 ph1 = {h10, h11}, pl1 = {l10, l11};
            __nv_bfloat16 h20, l20, h21, l21, h30, l30, h31, l31;
            cvt_split(s[2 * t + 1][0], h20, l20);
            cvt_split(s[2 * t + 1][1], h21, l21);
            cvt_split(s[2 * t + 1][2], h30, l30);
            cvt_split(s[2 * t + 1][3], h31, l31);
            __nv_bfloat162 ph2 = {h20, h21}, pl2 = {l20, l21};
            __nv_bfloat162 ph3 = {h30, h31}, pl3 = {l30, l31};
            pfh[t][0] = *(uint32_t*)&ph0;
            pfh[t][1] = *(uint32_t*)&ph1;
            pfh[t][2] = *(uint32_t*)&ph2;
            pfh[t][3] = *(uint32_t*)&ph3;
            pfl[t][0] = *(uint32_t*)&pl0;
            pfl[t][1] = *(uint32_t*)&pl1;
            pfl[t][2] = *(uint32_t*)&pl2;
            pfl[t][3] = *(uint32_t*)&pl3;
        }

        // ---- O += P V (3-pass split) ----
#pragma unroll
        for (int dt = 0; dt < 8; dt++) {
            const int vr = dt * 8 + lr;
#pragma unroll
            for (int t = 0; t < 4; t++) {
                const int jc = t * 16 + lc * 2;
                uint32_t bhf[2], blf[2];
                bhf[0] = *(const uint32_t*)&S->Vh[vr][jc];
                bhf[1] = *(const uint32_t*)&S->Vh[vr][jc + 8];
                blf[0] = *(const uint32_t*)&S->Vl[vr][jc];
                blf[1] = *(const uint32_t*)&S->Vl[vr][jc + 8];
                mma16816(o[dt], pfh[t], bhf);
                mma16816(o[dt], pfh[t], blf);
                mma16816(o[dt], pfl[t], bhf);
            }
        }
    }

    // ---- Output: y split bf16 hi/lo; y[b, t, h*64+d] = o / l ----
    const int hh = bh % HH, bb = bh / HH;
    const float inv0 = 1.0f / l_run[0];
    const float inv1 = 1.0f / l_run[1];
    const int row0 = it * 64 + warp * 16 + lr;
#pragma unroll
    for (int nt = 0; nt < 8; nt++) {
        const int d = nt * 8 + lc * 2;
        const size_t o0 = ((size_t)bb * TT + row0) * CC + hh * DD + d;
        const size_t o1 = o0 + (size_t)8 * CC;
        __nv_bfloat16 hx, lx, hy, ly;
        cvt_split(o[nt][0] * inv0, hx, lx);
        cvt_split(o[nt][1] * inv0, hy, ly);
        __nv_bfloat162 h2 = {hx, hy}, l2 = {lx, ly};
        *(__nv_bfloat162*)&g_yh[o0] = h2;
        *(__nv_bfloat162*)&g_yl[o0] = l2;
        cvt_split(o[nt][2] * inv1, hx, lx);
        cvt_split(o[nt][3] * inv1, hy, ly);
        __nv_bfloat162 h3 = {hx, hy}, l3 = {lx, ly};
        *(__nv_bfloat162*)&g_yh[o1] = h3;
        *(__nv_bfloat162*)&g_yl[o1] = l3;
    }
}

// ---------------------------------------------------------------------------
extern "C" void kernel_launch(void* const* d_in, const int* in_sizes, int n_in,
                              void* d_out, int out_size)
{
    const float* x      = (const float*)d_in[0];
    const float* w_attn = (const float*)d_in[1];
    const float* b_attn = (const float*)d_in[2];
    const float* w_proj = (const float*)d_in[3];
    const float* b_proj = (const float*)d_in[4];
    const float* rel    = (const float*)d_in[5];
    float* out = (float*)d_out;

    cudaFuncSetAttribute(tc_gemm_kernel,
                         cudaFuncAttributeMaxDynamicSharedMemorySize, GEMM_SMEM);
    cudaFuncSetAttribute(flash_kernel,
                         cudaFuncAttributeMaxDynamicSharedMemorySize,
                         (int)sizeof(FlashSmem));

    split_x_kernel<<<(MR * CC) / (256 * 4), 256>>>(x);
    tsplit_kernel<<<dim3(N3 / 32, CC / 32), 256>>>(w_attn, N3, 0);
    tsplit_kernel<<<dim3(CC / 32, CC / 32), 256>>>(w_proj, CC, 1);
    tc_gemm_kernel<<<dim3(N3 / 128, MR / 128), 256, GEMM_SMEM>>>(
        b_attn, rel, nullptr, 0);
    flash_kernel<<<dim3(TT / 64, BQ * HH), 128, sizeof(FlashSmem)>>>();
    tc_gemm_kernel<<<dim3(CC / 128, MR / 128), 256, GEMM_SMEM>>>(
        b_proj, rel, out, 1);
}

// round 11
// speedup vs baseline: 1.0729x; 1.0505x over previous
#include <cuda_runtime.h>
#include <cuda_bf16.h>
#include <cstdint>

#define BQ 8
#define TT 1024
#define CC 768
#define HH 12
#define DD 64
#define MR (BQ*TT)
#define N3 (3*CC)

// Scratch (allocation-free rule: __device__ globals)
__device__ __align__(16) __nv_bfloat16 g_xh[(size_t)MR*CC], g_xl[(size_t)MR*CC];
__device__ __align__(16) __nv_bfloat16 g_wth[(size_t)N3*CC], g_wtl[(size_t)N3*CC];
__device__ __align__(16) __nv_bfloat16 g_pth[(size_t)CC*CC], g_ptl[(size_t)CC*CC];
__device__ __align__(16) __nv_bfloat16 g_qh[(size_t)BQ*HH*TT*DD], g_ql[(size_t)BQ*HH*TT*DD];
__device__ __align__(16) __nv_bfloat16 g_kh[(size_t)BQ*HH*TT*DD], g_kl[(size_t)BQ*HH*TT*DD];
__device__ __align__(16) float g_v[(size_t)BQ*HH*TT*DD];
__device__ __align__(16) __nv_bfloat16 g_yh[(size_t)MR*CC], g_yl[(size_t)MR*CC];

// ---------------------------------------------------------------------------
// helpers
// ---------------------------------------------------------------------------
__device__ __forceinline__ void mma16816(float* d, const uint32_t* a, const uint32_t* b) {
    asm volatile(
        "mma.sync.aligned.m16n8k16.row.col.f32.bf16.bf16.f32 "
        "{%0,%1,%2,%3}, {%4,%5,%6,%7}, {%8,%9}, {%0,%1,%2,%3};\n"
        : "+f"(d[0]), "+f"(d[1]), "+f"(d[2]), "+f"(d[3])
        : "r"(a[0]), "r"(a[1]), "r"(a[2]), "r"(a[3]), "r"(b[0]), "r"(b[1]));
}

struct __align__(8) BF4 { __nv_bfloat16 a, b, c, d; };

__device__ __forceinline__ void cvt_split(float x, __nv_bfloat16& h, __nv_bfloat16& l) {
    h = __float2bfloat16(x);
    l = __float2bfloat16(x - __bfloat162float(h));
}

// fast 2^y for y <= 0, FMA-pipe only. ~1.5e-5 max rel error.
__device__ __forceinline__ float exp2p(float y) {
    y = fmaxf(y, -126.f);
    float fi = floorf(y);
    float f = y - fi;
    float p = 1.f + f * (0.6931472f + f * (0.2402265f + f * (0.0555041f +
              f * (0.0096181f + f * (0.0013334f + f * 0.0001546f)))));
    return __int_as_float(__float_as_int(p) + ((int)fi << 23));
}
#define LOG2E 1.4426950408889634f

// ---------------------------------------------------------------------------
// Split X elementwise: fp32 -> bf16 hi/lo
// ---------------------------------------------------------------------------
__global__ void split_x_kernel(const float* __restrict__ x) {
    const size_t i = ((size_t)blockIdx.x * 256 + threadIdx.x) * 4;
    float4 v = *(const float4*)(x + i);
    BF4 h, l;
    cvt_split(v.x, h.a, l.a);
    cvt_split(v.y, h.b, l.b);
    cvt_split(v.z, h.c, l.c);
    cvt_split(v.w, h.d, l.d);
    *(BF4*)&g_xh[i] = h;
    *(BF4*)&g_xl[i] = l;
}

// ---------------------------------------------------------------------------
// Transpose + split: W [768][N] fp32 -> [N][768] bf16 hi/lo. Destination
// globals selected in device code (host-passed __device__ symbols are UB).
// ---------------------------------------------------------------------------
__global__ void tsplit_kernel(const float* __restrict__ W, int N, int which) {
    __nv_bfloat16* outh = (which == 0) ? g_wth : g_pth;
    __nv_bfloat16* outl = (which == 0) ? g_wtl : g_ptl;
    __shared__ float t[32][33];
    const int n0 = blockIdx.x * 32, k0 = blockIdx.y * 32;
    const int tx = threadIdx.x & 31, ty = threadIdx.x >> 5;
#pragma unroll
    for (int i = 0; i < 4; i++)
        t[ty + i * 8][tx] = W[(size_t)(k0 + ty + i * 8) * N + n0 + tx];
    __syncthreads();
#pragma unroll
    for (int i = 0; i < 4; i++) {
        float v = t[tx][ty + i * 8];
        __nv_bfloat16 h, l;
        cvt_split(v, h, l);
        const size_t o = (size_t)(n0 + ty + i * 8) * CC + k0 + tx;
        outh[o] = h;
        outl[o] = l;
    }
}

// ---------------------------------------------------------------------------
// HMMA GEMM on pre-split bf16: C[8192 x N] = A * B^T (+bias)
// BM=128, BN=256, BK=32; 8 warps (2m x 4n), warp tile 64x64 -> 85B smem/MMA
// (was 128B at 64x32) since the kernel is smem-crossbar bound, not occupancy
// bound. Fragment loads interleaved per-mi between MMA groups. 3-pass split.
// mode 0: X*Wattn -> scatter q/k (bf16 split) + v (fp32); mode 1: Y*Wproj.
// ---------------------------------------------------------------------------
#define PAD 40
#define A_MAT (128 * PAD)                  // 5120 elems
#define B_MAT (256 * PAD)                  // 10240 elems
#define ST_ELEMS (2 * A_MAT + 2 * B_MAT)   // 30720 elems: Ah, Al, Bh, Bl
#define OFF_AL A_MAT
#define OFF_BH (2 * A_MAT)
#define OFF_BL (2 * A_MAT + B_MAT)
#define GEMM_SMEM (2 * ST_ELEMS * 2)       // 122880 bytes

__global__ __launch_bounds__(256, 1) void tc_gemm_kernel(
    const float* __restrict__ bias, const float* __restrict__ rel,
    float* __restrict__ out, int mode)
{
    extern __shared__ __nv_bfloat16 sm[];

    const __nv_bfloat16* Ah = (mode == 0) ? g_xh : g_yh;
    const __nv_bfloat16* Al = (mode == 0) ? g_xl : g_yl;
    const __nv_bfloat16* Bh = (mode == 0) ? g_wth : g_pth;
    const __nv_bfloat16* Bl = (mode == 0) ? g_wtl : g_ptl;

    const int tid = threadIdx.x;
    const int wid = tid >> 5, lane = tid & 31;
    const int n0 = blockIdx.x * 256;
    const int m0 = blockIdx.y * 128;

    const int warp_m = wid & 1;        // 2 tiles of 64 rows
    const int warp_n = wid >> 1;       // 4 tiles of 64 cols
    const int lr = lane >> 2;
    const int lc = lane & 3;

    // A loader: row = tid>>1 (0..127), k-offset = (tid&1)*16
    const int crowA = tid >> 1;
    const int ckoA = (tid & 1) * 16;
    const int soffA = crowA * PAD + ckoA;
    const __nv_bfloat16* gAh = Ah + (size_t)(m0 + crowA) * CC + ckoA;
    const __nv_bfloat16* gAl = Al + (size_t)(m0 + crowA) * CC + ckoA;
    // B loader: row = tid (0..255), full 32-k row per thread
    const int soffB = tid * PAD;
    const __nv_bfloat16* gBh = Bh + (size_t)(n0 + tid) * CC;
    const __nv_bfloat16* gBl = Bl + (size_t)(n0 + tid) * CC;

    float acc[4][8][4];
#pragma unroll
    for (int i = 0; i < 4; i++)
#pragma unroll
        for (int j = 0; j < 8; j++)
#pragma unroll
            for (int r = 0; r < 4; r++) acc[i][j][r] = 0.f;

    uint4 rA[4], rB[8];

    auto load_global = [&](int k0) {
        rA[0] = *(const uint4*)(gAh + k0);
        rA[1] = *(const uint4*)(gAh + k0 + 8);
        rA[2] = *(const uint4*)(gAl + k0);
        rA[3] = *(const uint4*)(gAl + k0 + 8);
#pragma unroll
        for (int c = 0; c < 4; c++) {
            rB[c] = *(const uint4*)(gBh + k0 + c * 8);
            rB[4 + c] = *(const uint4*)(gBl + k0 + c * 8);
        }
    };

    auto store_smem = [&](int buf) {
        __nv_bfloat16* base = sm + buf * ST_ELEMS;
        *(uint4*)(base + soffA) = rA[0];
        *(uint4*)(base + soffA + 8) = rA[1];
        *(uint4*)(base + OFF_AL + soffA) = rA[2];
        *(uint4*)(base + OFF_AL + soffA + 8) = rA[3];
#pragma unroll
        for (int c = 0; c < 4; c++) {
            *(uint4*)(base + OFF_BH + soffB + c * 8) = rB[c];
            *(uint4*)(base + OFF_BL + soffB + c * 8) = rB[4 + c];
        }
    };

    load_global(0);
    store_smem(0);
    __syncthreads();

    const int arow0 = warp_m * 64 + lr;
    const int brow0 = warp_n * 64 + lr;
    const int kcol0 = lc * 2;

    for (int s = 0; s < 24; s++) {
        if (s < 23) load_global((s + 1) * 32);

        const __nv_bfloat16* base = sm + (s & 1) * ST_ELEMS;
        const __nv_bfloat16* sAh = base;
        const __nv_bfloat16* sAl = base + OFF_AL;
        const __nv_bfloat16* sBh = base + OFF_BH;
        const __nv_bfloat16* sBl = base + OFF_BL;

#pragma unroll
        for (int ks = 0; ks < 2; ks++) {
            const int kc = ks * 16 + kcol0;
            uint32_t bh[8][2], bl[8][2];
#pragma unroll
            for (int ni = 0; ni < 8; ni++) {
                const int r = brow0 + ni * 8;
                bh[ni][0] = *(const uint32_t*)(sBh + r * PAD + kc);
                bh[ni][1] = *(const uint32_t*)(sBh + r * PAD + kc + 8);
                bl[ni][0] = *(const uint32_t*)(sBl + r * PAD + kc);
                bl[ni][1] = *(const uint32_t*)(sBl + r * PAD + kc + 8);
            }
#pragma unroll
            for (int mi = 0; mi < 4; mi++) {
                const int r = arow0 + mi * 16;
                uint32_t af[4];
                af[0] = *(const uint32_t*)(sAh + r * PAD + kc);
                af[1] = *(const uint32_t*)(sAh + (r + 8) * PAD + kc);
                af[2] = *(const uint32_t*)(sAh + r * PAD + kc + 8);
                af[3] = *(const uint32_t*)(sAh + (r + 8) * PAD + kc + 8);
#pragma unroll
                for (int ni = 0; ni < 8; ni++)
                    mma16816(acc[mi][ni], af, bh[ni]);
#pragma unroll
                for (int ni = 0; ni < 8; ni++)
                    mma16816(acc[mi][ni], af, bl[ni]);
                af[0] = *(const uint32_t*)(sAl + r * PAD + kc);
                af[1] = *(const uint32_t*)(sAl + (r + 8) * PAD + kc);
                af[2] = *(const uint32_t*)(sAl + r * PAD + kc + 8);
                af[3] = *(const uint32_t*)(sAl + (r + 8) * PAD + kc + 8);
#pragma unroll
                for (int ni = 0; ni < 8; ni++)
                    mma16816(acc[mi][ni], af, bh[ni]);
            }
        }

        if (s < 23) {
            store_smem((s + 1) & 1);
            __syncthreads();
        }
    }

    // ---- Epilogue (same formulas as R10; warp_n tile now 64 wide) ----
    const int seg = (mode == 0) ? (n0 / CC) : 0;

#pragma unroll
    for (int mi = 0; mi < 4; mi++) {
#pragma unroll
        for (int half = 0; half < 2; half++) {
            const int r = m0 + warp_m * 64 + mi * 16 + lr + half * 8;
#pragma unroll
            for (int ni = 0; ni < 8; ni++) {
                const int gc = n0 + warp_n * 64 + ni * 8 + lc * 2;
                float2 v;
                v.x = acc[mi][ni][half * 2 + 0] + bias[gc];
                v.y = acc[mi][ni][half * 2 + 1] + bias[gc + 1];
                if (mode == 0) {
                    const int bb = r >> 10, t = r & 1023;
                    const int cl = gc - seg * CC;
                    const int h = cl >> 6, d = cl & 63;
                    const size_t idx = (((size_t)bb * HH + h) * TT + t) * DD + d;
                    if (seg == 0) {
                        v.x *= 0.125f; v.y *= 0.125f;
                        __nv_bfloat16 hx, lx, hy, ly;
                        cvt_split(v.x, hx, lx);
                        cvt_split(v.y, hy, ly);
                        __nv_bfloat162 h2 = {hx, hy}, l2 = {lx, ly};
                        *(__nv_bfloat162*)&g_qh[idx] = h2;
                        *(__nv_bfloat162*)&g_ql[idx] = l2;
                    } else if (seg == 1) {
                        if (t > 0) {
                            float2 rv = *(const float2*)&rel[(size_t)(t - 1) * DD + d];
                            v.x += rv.x; v.y += rv.y;
                        }
                        __nv_bfloat16 hx, lx, hy, ly;
                        cvt_split(v.x, hx, lx);
                        cvt_split(v.y, hy, ly);
                        __nv_bfloat162 h2 = {hx, hy}, l2 = {lx, ly};
                        *(__nv_bfloat162*)&g_kh[idx] = h2;
                        *(__nv_bfloat162*)&g_kl[idx] = l2;
                    } else {
                        *(float2*)&g_v[idx] = v;
                    }
                } else {
                    *(float2*)&out[(size_t)r * CC + gc] = v;
                }
            }
        }
    }
}

// ---------------------------------------------------------------------------
// HMMA causal flash attention (R10-proven, unchanged).
// ---------------------------------------------------------------------------
#define FPAD 72

struct FlashSmem {
    __nv_bfloat16 Qh[64][FPAD], Ql[64][FPAD];
    __nv_bfloat16 Kh[64][FPAD], Kl[64][FPAD];
    __nv_bfloat16 Vh[64][FPAD], Vl[64][FPAD];
};

__global__ __launch_bounds__(128, 2) void flash_kernel()
{
    extern __shared__ char fsm_raw[];
    FlashSmem* S = reinterpret_cast<FlashSmem*>(fsm_raw);

    const int it = gridDim.x - 1 - blockIdx.x;
    const int bh = blockIdx.y;
    const size_t hb = (size_t)bh * TT * DD;
    const float* Vg = g_v + hb;

    const int tid = threadIdx.x;
    const int warp = tid >> 5, lane = tid & 31;
    const int lr = lane >> 2, lc = lane & 3;

    {
        const __nv_bfloat16* qhg = g_qh + hb + (size_t)it * 64 * DD;
        const __nv_bfloat16* qlg = g_ql + hb + (size_t)it * 64 * DD;
#pragma unroll
        for (int b = 0; b < 4; b++) {
            const int idx = tid + b * 128;
            const int row = idx >> 3, c8 = (idx & 7) * 8;
            *(uint4*)&S->Qh[row][c8] = *(const uint4*)(qhg + row * DD + c8);
            *(uint4*)&S->Ql[row][c8] = *(const uint4*)(qlg + row * DD + c8);
        }
    }
    __syncthreads();

    uint32_t qh[4][4], ql[4][4];
    const int qr = warp * 16 + lr;
#pragma unroll
    for (int t = 0; t < 4; t++) {
        const int kc = t * 16 + lc * 2;
        qh[t][0] = *(const uint32_t*)&S->Qh[qr][kc];
        qh[t][1] = *(const uint32_t*)&S->Qh[qr + 8][kc];
        qh[t][2] = *(const uint32_t*)&S->Qh[qr][kc + 8];
        qh[t][3] = *(const uint32_t*)&S->Qh[qr + 8][kc + 8];
        ql[t][0] = *(const uint32_t*)&S->Ql[qr][kc];
        ql[t][1] = *(const uint32_t*)&S->Ql[qr + 8][kc];
        ql[t][2] = *(const uint32_t*)&S->Ql[qr][kc + 8];
        ql[t][3] = *(const uint32_t*)&S->Ql[qr + 8][kc + 8];
    }

    float o[8][4];
#pragma unroll
    for (int nt = 0; nt < 8; nt++)
#pragma unroll
        for (int r = 0; r < 4; r++) o[nt][r] = 0.f;
    float m_run[2] = {-1e30f, -1e30f};
    float l_run[2] = {0.f, 0.f};

    for (int jt = 0; jt <= it; jt++) {
        __syncthreads();
        {
            const __nv_bfloat16* khg = g_kh + hb + (size_t)jt * 64 * DD;
            const __nv_bfloat16* klg = g_kl + hb + (size_t)jt * 64 * DD;
#pragma unroll
            for (int b = 0; b < 4; b++) {
                const int idx = tid + b * 128;
                const int row = idx >> 3, c8 = (idx & 7) * 8;
                *(uint4*)&S->Kh[row][c8] = *(const uint4*)(khg + row * DD + c8);
                *(uint4*)&S->Kl[row][c8] = *(const uint4*)(klg + row * DD + c8);
            }
        }
#pragma unroll
        for (int b = 0; b < 2; b++) {
            const int bi = tid + b * 128;
            const int jr = (bi >> 4) * 4, dc = (bi & 15) * 4;
            const float* vp = Vg + (size_t)(jt * 64 + jr) * DD + dc;
            float4 r0 = *(const float4*)(vp);
            float4 r1 = *(const float4*)(vp + DD);
            float4 r2 = *(const float4*)(vp + 2 * DD);
            float4 r3 = *(const float4*)(vp + 3 * DD);
            float col[4][4] = {
                {r0.x, r1.x, r2.x, r3.x},
                {r0.y, r1.y, r2.y, r3.y},
                {r0.z, r1.z, r2.z, r3.z},
                {r0.w, r1.w, r2.w, r3.w}};
#pragma unroll
            for (int j = 0; j < 4; j++) {
                BF4 h, l;
                cvt_split(col[j][0], h.a, l.a);
                cvt_split(col[j][1], h.b, l.b);
                cvt_split(col[j][2], h.c, l.c);
                cvt_split(col[j][3], h.d, l.d);
                *(BF4*)&S->Vh[dc + j][jr] = h;
                *(BF4*)&S->Vl[dc + j][jr] = l;
            }
        }
        __syncthreads();

        float s[8][4];
#pragma unroll
        for (int nt = 0; nt < 8; nt++)
#pragma unroll
            for (int r = 0; r < 4; r++) s[nt][r] = 0.f;
#pragma unroll
        for (int nt = 0; nt < 8; nt++) {
            const int kr = nt * 8 + lr;
#pragma unroll
            for (int t = 0; t < 4; t++) {
                const int kc = t * 16 + lc * 2;
                uint32_t bhf[2], blf[2];
                bhf[0] = *(const uint32_t*)&S->Kh[kr][kc];
                bhf[1] = *(const uint32_t*)&S->Kh[kr][kc + 8];
                blf[0] = *(const uint32_t*)&S->Kl[kr][kc];
                blf[1] = *(const uint32_t*)&S->Kl[kr][kc + 8];
                mma16816(s[nt], qh[t], bhf);
                mma16816(s[nt], qh[t], blf);
                mma16816(s[nt], ql[t], bhf);
            }
        }

        if (jt == it) {
#pragma unroll
            for (int nt = 0; nt < 8; nt++) {
#pragma unroll
                for (int r = 0; r < 4; r++) {
                    const int col = nt * 8 + lc * 2 + (r & 1);
                    const int row = warp * 16 + lr + ((r >> 1) * 8);
                    if (col > row) s[nt][r] = -1e30f;
                }
            }
        }

        float mnew[2], fscale[2];
#pragma unroll
        for (int h = 0; h < 2; h++) {
            float m = -1e30f;
#pragma unroll
            for (int nt = 0; nt < 8; nt++)
                m = fmaxf(m, fmaxf(s[nt][h * 2], s[nt][h * 2 + 1]));
            m = fmaxf(m, __shfl_xor_sync(0xFFFFFFFF, m, 1));
            m = fmaxf(m, __shfl_xor_sync(0xFFFFFFFF, m, 2));
            mnew[h] = fmaxf(m_run[h], m);
            fscale[h] = exp2p((m_run[h] - mnew[h]) * LOG2E);
            m_run[h] = mnew[h];
        }

        float rsum[2] = {0.f, 0.f};
#pragma unroll
        for (int nt = 0; nt < 8; nt++) {
#pragma unroll
            for (int r = 0; r < 4; r++) {
                const int h = r >> 1;
                float p = exp2p((s[nt][r] - mnew[h]) * LOG2E);
                s[nt][r] = p;
                rsum[h] += p;
            }
        }
#pragma unroll
        for (int h = 0; h < 2; h++) {
            rsum[h] += __shfl_xor_sync(0xFFFFFFFF, rsum[h], 1);
            rsum[h] += __shfl_xor_sync(0xFFFFFFFF, rsum[h], 2);
            l_run[h] = l_run[h] * fscale[h] + rsum[h];
        }

#pragma unroll
        for (int nt = 0; nt < 8; nt++) {
#pragma unroll
            for (int r = 0; r < 4; r++) o[nt][r] *= fscale[r >> 1];
        }

        uint32_t pfh[4][4], pfl[4][4];
#pragma unroll
        for (int t = 0; t < 4; t++) {
            __nv_bfloat16 h00, l00, h01, l01, h10, l10, h11, l11;
            cvt_split(s[2 * t][0], h00, l00);
            cvt_split(s[2 * t][1], h01, l01);
            cvt_split(s[2 * t][2], h10, l10);
            cvt_split(s[2 * t][3], h11, l11);
            __nv_bfloat162 ph0 = {h00, h01}, pl0 = {l00, l01};
            __nv_bfloat162 ph1 = {h10, h11}, pl1 = {l10, l11};
            __nv_bfloat16 h20, l20, h21, l21, h30, l30, h31, l31;
            cvt_split(s[2 * t + 1][0], h20, l20);
            cvt_split(s[2 * t + 1][1], h21, l21);
            cvt_split(s[2 * t + 1][2], h30, l30);
            cvt_split(s[2 * t + 1][3], h31, l31);
            __nv_bfloat162 ph2 = {h20, h21}, pl2 = {l20, l21};
            __nv_bfloat162 ph3 = {h30, h31}, pl3 = {l30, l31};
            pfh[t][0] = *(uint32_t*)&ph0;
            pfh[t][1] = *(uint32_t*)&ph1;
            pfh[t][2] = *(uint32_t*)&ph2;
            pfh[t][3] = *(uint32_t*)&ph3;
            pfl[t][0] = *(uint32_t*)&pl0;
            pfl[t][1] = *(uint32_t*)&pl1;
            pfl[t][2] = *(uint32_t*)&pl2;
            pfl[t][3] = *(uint32_t*)&pl3;
        }

#pragma unroll
        for (int dt = 0; dt < 8; dt++) {
            const int vr = dt * 8 + lr;
#pragma unroll
            for (int t = 0; t < 4; t++) {
                const int jc = t * 16 + lc * 2;
                uint32_t bhf[2], blf[2];
                bhf[0] = *(const uint32_t*)&S->Vh[vr][jc];
                bhf[1] = *(const uint32_t*)&S->Vh[vr][jc + 8];
                blf[0] = *(const uint32_t*)&S->Vl[vr][jc];
                blf[1] = *(const uint32_t*)&S->Vl[vr][jc + 8];
                mma16816(o[dt], pfh[t], bhf);
                mma16816(o[dt], pfh[t], blf);
                mma16816(o[dt], pfl[t], bhf);
            }
        }
    }

    const int hh = bh % HH, bb = bh / HH;
    const float inv0 = 1.0f / l_run[0];
    const float inv1 = 1.0f / l_run[1];
    const int row0 = it * 64 + warp * 16 + lr;
#pragma unroll
    for (int nt = 0; nt < 8; nt++) {
        const int d = nt * 8 + lc * 2;
        const size_t o0 = ((size_t)bb * TT + row0) * CC + hh * DD + d;
        const size_t o1 = o0 + (size_t)8 * CC;
        __nv_bfloat16 hx, lx, hy, ly;
        cvt_split(o[nt][0] * inv0, hx, lx);
        cvt_split(o[nt][1] * inv0, hy, ly);
        __nv_bfloat162 h2 = {hx, hy}, l2 = {lx, ly};
        *(__nv_bfloat162*)&g_yh[o0] = h2;
        *(__nv_bfloat162*)&g_yl[o0] = l2;
        cvt_split(o[nt][2] * inv1, hx, lx);
        cvt_split(o[nt][3] * inv1, hy, ly);
        __nv_bfloat162 h3 = {hx, hy}, l3 = {lx, ly};
        *(__nv_bfloat162*)&g_yh[o1] = h3;
        *(__nv_bfloat162*)&g_yl[o1] = l3;
    }
}

// ---------------------------------------------------------------------------
extern "C" void kernel_launch(void* const* d_in, const int* in_sizes, int n_in,
                              void* d_out, int out_size)
{
    const float* x      = (const float*)d_in[0];
    const float* w_attn = (const float*)d_in[1];
    const float* b_attn = (const float*)d_in[2];
    const float* w_proj = (const float*)d_in[3];
    const float* b_proj = (const float*)d_in[4];
    const float* rel    = (const float*)d_in[5];
    float* out = (float*)d_out;

    cudaFuncSetAttribute(tc_gemm_kernel,
                         cudaFuncAttributeMaxDynamicSharedMemorySize, GEMM_SMEM);
    cudaFuncSetAttribute(flash_kernel,
                         cudaFuncAttributeMaxDynamicSharedMemorySize,
                         (int)sizeof(FlashSmem));

    split_x_kernel<<<(MR * CC) / (256 * 4), 256>>>(x);
    tsplit_kernel<<<dim3(N3 / 32, CC / 32), 256>>>(w_attn, N3, 0);
    tsplit_kernel<<<dim3(CC / 32, CC / 32), 256>>>(w_proj, CC, 1);
    tc_gemm_kernel<<<dim3(N3 / 256, MR / 128), 256, GEMM_SMEM>>>(
        b_attn, rel, nullptr, 0);
    flash_kernel<<<dim3(TT / 64, BQ * HH), 128, sizeof(FlashSmem)>>>();
    tc_gemm_kernel<<<dim3(CC / 256, MR / 128), 256, GEMM_SMEM>>>(
        b_proj, rel, out, 1);
}